// round 9
// baseline (speedup 1.0000x reference)
#include <cuda_runtime.h>
#include <cuda_bf16.h>
#include <cstdint>

#define B_ 8
#define P_ 64
#define S_ 256
#define D_ 256

// ---------------- device scratch ----------------
__device__ __align__(16) __nv_bfloat16 g_hi[(size_t)B_ * P_ * S_ * D_];  // 64MB, chunk-blocked
__device__ __align__(16) __nv_bfloat16 g_lo[(size_t)B_ * P_ * S_ * D_];  // 64MB
__device__ float g_partials[P_ * 32 * 5];
__device__ float g_scale[P_];
__device__ float g_bias[P_];
__device__ int   g_cnt[P_];
__device__ int   g_cnt2[P_];
__device__ int   g_flag[P_];

__device__ __forceinline__ uint32_t smem_to_u32(const void* p) {
    uint32_t a;
    asm("{ .reg .u64 t; cvta.to.shared.u64 t, %1; cvt.u32.u64 %0, t; }" : "=r"(a) : "l"(p));
    return a;
}

#define LDSM4(d0, d1, d2, d3, a) \
    asm volatile("ldmatrix.sync.aligned.m8n8.x4.shared.b16 {%0,%1,%2,%3}, [%4];" \
                 : "=r"(d0), "=r"(d1), "=r"(d2), "=r"(d3) : "r"(a))

#define HMMA(c, a0, a1, a2, a3, b0, b1) \
    asm volatile("mma.sync.aligned.m16n8k16.row.col.f32.bf16.bf16.f32 " \
                 "{%0,%1,%2,%3}, {%4,%5,%6,%7}, {%8,%9}, {%0,%1,%2,%3};" \
                 : "+f"((c)[0]), "+f"((c)[1]), "+f"((c)[2]), "+f"((c)[3]) \
                 : "r"(a0), "r"(a1), "r"(a2), "r"(a3), "r"(b0), "r"(b1))

#define CP_ASYNC16(dst, src) \
    asm volatile("cp.async.cg.shared.global [%0], [%1], 16;" :: "r"(dst), "l"(src))
#define CP_COMMIT() asm volatile("cp.async.commit_group;" ::: "memory")
#define CP_WAIT0()  asm volatile("cp.async.wait_group 0;" ::: "memory")

// ---------------- smem layout (bytes) ----------------
constexpr int ROWB  = 80;                 // 32 bf16 = 64B + 16B pad (ldmatrix conflict-free)
constexpr int CHB   = 256 * ROWB;         // 20480 per hi or lo buffer
// buffers: [hi0][lo0][hi1][lo1]
constexpr int SMEM_BYTES = 4 * CHB;       // 81920 -> 2 CTAs/SM
// epilogue overlay:
constexpr int OFF_XSE  = 0;               // 64*256*4 = 65536
constexpr int OFF_REDP = 65536;           // 64*17*4 = 4352
constexpr int OFF_RS   = OFF_REDP + 4352; // 256
constexpr int OFF_S2   = OFF_RS + 256;    // 256
constexpr int OFF_RED  = OFF_S2 + 256;    // 256
constexpr int OFF_W8   = OFF_RED + 256;   // 32
constexpr int OFF_BC   = OFF_W8 + 32;     // 8   (total 70696 <= 81920)

// =====================================================================
// Pre-pass: x (fp32) -> hi/lo bf16, chunk-blocked layout:
//   dst elem index = bp*65536 + kc*8192 + row*32 + col32
// =====================================================================
__global__ void __launch_bounds__(256)
da_prep_kernel(const float* __restrict__ x)
{
    size_t f = (size_t)blockIdx.x * 256 + threadIdx.x;   // float4 id, 8388608 total
    float4 v = __ldg(reinterpret_cast<const float4*>(x) + f);
    size_t e = f * 4;
    int col = (int)(e & 255);
    int rg  = (int)(e >> 8);          // bp*256 + row
    int bp  = rg >> 8, r = rg & 255;
    int kc  = col >> 5, c = col & 31;
    size_t dst = ((size_t)bp * 8 + kc) * 8192 + r * 32 + c;

    __nv_bfloat162 h01 = __floats2bfloat162_rn(v.x, v.y);
    __nv_bfloat162 h23 = __floats2bfloat162_rn(v.z, v.w);
    __nv_bfloat162 l01 = __floats2bfloat162_rn(v.x - __low2float(h01),
                                               v.y - __high2float(h01));
    __nv_bfloat162 l23 = __floats2bfloat162_rn(v.z - __low2float(h23),
                                               v.w - __high2float(h23));
    *reinterpret_cast<uint2*>(g_hi + dst) =
        make_uint2(*reinterpret_cast<uint32_t*>(&h01), *reinterpret_cast<uint32_t*>(&h23));
    *reinterpret_cast<uint2*>(g_lo + dst) =
        make_uint2(*reinterpret_cast<uint32_t*>(&l01), *reinterpret_cast<uint32_t*>(&l23));
}

// =====================================================================
// Main: CTA = (b, p, q): rows [q*64, q*64+64). 256 thr, 2 CTA/SM.
// Mainloop: cp.async bf16 tiles (double-buffered) + HMMA only.
// =====================================================================
__global__ void __launch_bounds__(256, 2)
da_fused_kernel(const float* __restrict__ x, const float* __restrict__ w,
                const float* __restrict__ gamma, const float* __restrict__ beta,
                float* __restrict__ out)
{
    extern __shared__ __align__(16) char sm[];
    const uint32_t smb = smem_to_u32(sm);
    const int tid = threadIdx.x, wid = tid >> 5, lane = tid & 31;
    const int bx = blockIdx.x;                 // 0..31 = b*4 + q
    const int b = bx >> 2, q = bx & 3;
    const int p = blockIdx.y;
    const int bp = b * P_ + p;
    const int m0 = q * 64;
    const float* xbp = x + (size_t)bp * (S_ * D_);
    const __nv_bfloat16* hib = g_hi + (size_t)bp * 65536;
    const __nv_bfloat16* lob = g_lo + (size_t)bp * 65536;

    const int warp_m = wid >> 2;   // 0..1 : 32 m-rows
    const int warp_n = wid & 3;    // 0..3 : 64 n-cols

    float acc[2][8][4];
    #pragma unroll
    for (int mi = 0; mi < 2; ++mi)
        #pragma unroll
        for (int nf = 0; nf < 8; ++nf)
            #pragma unroll
            for (int qq = 0; qq < 4; ++qq) acc[mi][nf][qq] = 0.f;

    // ldmatrix per-lane addressing (buffer 0 base; +(kc&1)*2*CHB at use, +CHB for lo)
    const uint32_t lrow = lane & 15;
    const uint32_t lcol = (lane >> 4) * 16;
    uint32_t aaddr[2], baddr[4];
    #pragma unroll
    for (int mi = 0; mi < 2; ++mi)
        aaddr[mi] = smb + (uint32_t)(m0 + warp_m * 32 + mi * 16 + lrow) * ROWB + lcol;
    #pragma unroll
    for (int nj = 0; nj < 4; ++nj)
        baddr[nj] = smb + (uint32_t)(warp_n * 64 + nj * 16 + lrow) * ROWB + lcol;

    // cp.async mapping: thread = one row, 4+4 granules of 16B (hi then lo)
    // src row bytes: row*64 ; dst row bytes: row*80
    const uint32_t drow = (uint32_t)tid * ROWB;

    // ---- prologue: chunk 0 into buffer 0 ----
    {
        const char* sh = reinterpret_cast<const char*>(hib) + (size_t)tid * 64;
        const char* sl = reinterpret_cast<const char*>(lob) + (size_t)tid * 64;
        #pragma unroll
        for (int g = 0; g < 4; ++g) {
            CP_ASYNC16(smb + drow + g * 16, sh + g * 16);
            CP_ASYNC16(smb + CHB + drow + g * 16, sl + g * 16);
        }
        CP_COMMIT();
        CP_WAIT0();
    }
    __syncthreads();

    // ================= mainloop: 8 chunks of K=32 =================
    for (int kc = 0; kc < 8; ++kc) {
        // issue next chunk's copies first (hidden behind MMA)
        if (kc < 7) {
            const uint32_t nb = (uint32_t)((kc + 1) & 1) * (2 * CHB);
            const char* sh = reinterpret_cast<const char*>(hib) +
                             (size_t)(kc + 1) * 16384 + (size_t)tid * 64;
            const char* sl = reinterpret_cast<const char*>(lob) +
                             (size_t)(kc + 1) * 16384 + (size_t)tid * 64;
            #pragma unroll
            for (int g = 0; g < 4; ++g) {
                CP_ASYNC16(smb + nb + drow + g * 16, sh + g * 16);
                CP_ASYNC16(smb + nb + CHB + drow + g * 16, sl + g * 16);
            }
            CP_COMMIT();
        }

        // MMA on buffer[kc&1]
        const uint32_t bufo = (uint32_t)(kc & 1) * (2 * CHB);
        #pragma unroll
        for (int ks = 0; ks < 2; ++ks) {
            const uint32_t ko = bufo + (uint32_t)ks * 32;
            uint32_t ah[2][4], al[2][4];
            #pragma unroll
            for (int mi = 0; mi < 2; ++mi) {
                LDSM4(ah[mi][0], ah[mi][1], ah[mi][2], ah[mi][3], aaddr[mi] + ko);
                LDSM4(al[mi][0], al[mi][1], al[mi][2], al[mi][3], aaddr[mi] + ko + CHB);
            }
            #pragma unroll
            for (int nj = 0; nj < 4; ++nj) {
                uint32_t bh[4], bl[4];
                LDSM4(bh[0], bh[1], bh[2], bh[3], baddr[nj] + ko);
                LDSM4(bl[0], bl[1], bl[2], bl[3], baddr[nj] + ko + CHB);
                #pragma unroll
                for (int nk = 0; nk < 2; ++nk) {
                    const int nf = nj * 2 + nk;
                    #pragma unroll
                    for (int mi = 0; mi < 2; ++mi) {
                        HMMA(acc[mi][nf], ah[mi][0], ah[mi][1], ah[mi][2], ah[mi][3],
                             bh[nk], bh[2 + nk]);                          // hi*hi
                        HMMA(acc[mi][nf], al[mi][0], al[mi][1], al[mi][2], al[mi][3],
                             bh[nk], bh[2 + nk]);                          // lo*hi
                        HMMA(acc[mi][nf], ah[mi][0], ah[mi][1], ah[mi][2], ah[mi][3],
                             bl[nk], bl[2 + nk]);                          // hi*lo
                    }
                }
            }
        }

        if (kc < 7) CP_WAIT0();
        __syncthreads();
    }
    __syncthreads();   // buffers dead -> overlay usable

    // ================= fold W into per-row partials =================
    float* redp = reinterpret_cast<float*>(sm + OFF_REDP);
    const float* wp = w + ((size_t)p << 16);
    #pragma unroll
    for (int mi = 0; mi < 2; ++mi)
        #pragma unroll
        for (int half = 0; half < 2; ++half) {
            int rl = warp_m * 32 + mi * 16 + (lane >> 2) + half * 8;   // 0..63 local
            const float* wr = wp + (size_t)(m0 + rl) * 256 + warp_n * 64 + (lane & 3) * 2;
            float part = 0.f;
            #pragma unroll
            for (int nf = 0; nf < 8; ++nf) {
                float2 wv = __ldg(reinterpret_cast<const float2*>(wr + nf * 8));
                part = fmaf(acc[mi][nf][half * 2 + 0], wv.x, part);
                part = fmaf(acc[mi][nf][half * 2 + 1], wv.y, part);
            }
            redp[rl * 17 + warp_n * 4 + (lane & 3)] = part;
        }

    // ================= re-read own x rows into smem + row sums =================
    float* xs   = reinterpret_cast<float*>(sm + OFF_XSE);
    float* rssm = reinterpret_cast<float*>(sm + OFF_RS);
    float* s2sm = reinterpret_cast<float*>(sm + OFF_S2);
    #pragma unroll
    for (int j = 0; j < 8; ++j) {
        int r = wid * 8 + j;                       // 0..63 local
        const float* xr = xbp + (size_t)(m0 + r) * 256;
        float4 v0 = __ldg(reinterpret_cast<const float4*>(xr + lane * 4));
        float4 v1 = __ldg(reinterpret_cast<const float4*>(xr + 128 + lane * 4));
        *reinterpret_cast<float4*>(xs + r * 256 + lane * 4) = v0;
        *reinterpret_cast<float4*>(xs + r * 256 + 128 + lane * 4) = v1;
        float rsv = v0.x + v0.y + v0.z + v0.w + v1.x + v1.y + v1.z + v1.w;
        float s2v = v0.x * v0.x + v0.y * v0.y + v0.z * v0.z + v0.w * v0.w
                  + v1.x * v1.x + v1.y * v1.y + v1.z * v1.z + v1.w * v1.w;
        #pragma unroll
        for (int o = 16; o; o >>= 1) {
            rsv += __shfl_xor_sync(0xffffffffu, rsv, o);
            s2v += __shfl_xor_sync(0xffffffffu, s2v, o);
        }
        if (lane == 0) { rssm[r] = rsv; s2sm[r] = s2v; }
    }
    __syncthreads();

    // ================= finalize red + BN partials =================
    float* redsm = reinterpret_cast<float*>(sm + OFF_RED);
    float vals[5] = {0.f, 0.f, 0.f, 0.f, 0.f};
    if (tid < 64) {
        float rsum = 0.f;
        #pragma unroll
        for (int l = 0; l < 16; ++l) rsum += redp[tid * 17 + l];
        float red = rsum * 0.0625f;    // 1/sqrt(256)
        redsm[tid] = red;
        float xr = rssm[tid], x2 = s2sm[tid];
        vals[0] = xr; vals[1] = x2; vals[2] = red; vals[3] = red * red; vals[4] = red * xr;
    }
    float* w8 = reinterpret_cast<float*>(sm + OFF_W8);
    float out5[5];
    #pragma unroll
    for (int qq = 0; qq < 5; ++qq) {
        float v = vals[qq];
        #pragma unroll
        for (int o = 16; o; o >>= 1) v += __shfl_xor_sync(0xffffffffu, v, o);
        if (lane == 0) w8[wid] = v;
        __syncthreads();
        if (tid == 0) {
            float r = 0.f;
            for (int t = 0; t < 8; ++t) r += w8[t];
            out5[qq] = r;
        }
        __syncthreads();
    }

    // ================= cross-CTA BN handshake (32 CTAs per channel) =================
    float* bc = reinterpret_cast<float*>(sm + OFF_BC);
    if (tid == 0) {
        int slot = (p * 32 + bx) * 5;
        #pragma unroll
        for (int qq = 0; qq < 5; ++qq) g_partials[slot + qq] = out5[qq];
        __threadfence();
        int o = atomicAdd(&g_cnt[p], 1);
        if (o == 31) {
            __threadfence();
            float sx = 0.f, sx2 = 0.f, sr = 0.f, sr2 = 0.f, cr = 0.f;
            for (int c = 0; c < 32; ++c) {
                const float* qp = g_partials + (p * 32 + c) * 5;
                sx += qp[0]; sx2 += qp[1]; sr += qp[2]; sr2 += qp[3]; cr += qp[4];
            }
            const float N = (float)(B_ * S_ * D_);
            float sumy  = sx + (float)D_ * sr;
            float sumy2 = sx2 + 2.f * cr + (float)D_ * sr2;
            float mean = sumy / N;
            float var  = sumy2 / N - mean * mean;
            float sc = __ldg(gamma + p) * rsqrtf(var + 1e-5f);
            g_scale[p] = sc;
            g_bias[p]  = __ldg(beta + p) - mean * sc;
            __threadfence();
            atomicExch(&g_flag[p], 1);
        }
        volatile int* fl = (volatile int*)&g_flag[p];
        while (*fl == 0) __nanosleep(64);
        __threadfence();
        bc[0] = g_scale[p];
        bc[1] = g_bias[p];
        int o2 = atomicAdd(&g_cnt2[p], 1);
        if (o2 == 31) {        // all consumers done: reset for next graph replay
            g_flag[p] = 0; g_cnt[p] = 0; g_cnt2[p] = 0;
        }
    }
    __syncthreads();
    const float sc = bc[0], bi = bc[1];

    // ================= output: out = (x + red) * sc + bi =================
    float* ob = out + ((size_t)bp << 16) + (size_t)m0 * 256;
    #pragma unroll
    for (int j = 0; j < 8; ++j) {
        int r = wid * 8 + j;
        float red = redsm[r];
        #pragma unroll
        for (int it = 0; it < 2; ++it) {
            float4 v = *reinterpret_cast<const float4*>(xs + r * 256 + it * 128 + lane * 4);
            v.x = fmaf(v.x + red, sc, bi);
            v.y = fmaf(v.y + red, sc, bi);
            v.z = fmaf(v.z + red, sc, bi);
            v.w = fmaf(v.w + red, sc, bi);
            *reinterpret_cast<float4*>(ob + (size_t)r * 256 + it * 128 + lane * 4) = v;
        }
    }
}

// =====================================================================
extern "C" void kernel_launch(void* const* d_in, const int* in_sizes, int n_in,
                              void* d_out, int out_size)
{
    const float* x     = (const float*)d_in[0];
    const float* w     = (const float*)d_in[1];
    const float* gamma = (const float*)d_in[2];
    const float* beta  = (const float*)d_in[3];
    float* out = (float*)d_out;

    cudaFuncSetAttribute(da_fused_kernel,
                         cudaFuncAttributeMaxDynamicSharedMemorySize, SMEM_BYTES);

    da_prep_kernel<<<32768, 256>>>(x);
    dim3 grid(32, P_);   // blockIdx.x = b*4+q (channel CTAs contiguous), blockIdx.y = p
    da_fused_kernel<<<grid, 256, SMEM_BYTES>>>(x, w, gamma, beta, out);
}

// round 10
// speedup vs baseline: 1.3922x; 1.3922x over previous
#include <cuda_runtime.h>
#include <cuda_bf16.h>
#include <cstdint>

#define B_ 8
#define P_ 64
#define S_ 256
#define D_ 256

// ---------------- device scratch (zero-init at load; reset each run) ----------------
__device__ float g_partials[P_ * 32 * 5];
__device__ float g_scale[P_];
__device__ float g_bias[P_];
__device__ int   g_cnt[P_];
__device__ int   g_cnt2[P_];
__device__ int   g_flag[P_];

__device__ __forceinline__ uint32_t smem_to_u32(const void* p) {
    uint32_t a;
    asm("{ .reg .u64 t; cvta.to.shared.u64 t, %1; cvt.u32.u64 %0, t; }" : "=r"(a) : "l"(p));
    return a;
}

#define LDSM4(d0, d1, d2, d3, a) \
    asm volatile("ldmatrix.sync.aligned.m8n8.x4.shared.b16 {%0,%1,%2,%3}, [%4];" \
                 : "=r"(d0), "=r"(d1), "=r"(d2), "=r"(d3) : "r"(a))

#define HMMA(c, a0, a1, a2, a3, b0, b1) \
    asm volatile("mma.sync.aligned.m16n8k16.row.col.f32.bf16.bf16.f32 " \
                 "{%0,%1,%2,%3}, {%4,%5,%6,%7}, {%8,%9}, {%0,%1,%2,%3};" \
                 : "+f"((c)[0]), "+f"((c)[1]), "+f"((c)[2]), "+f"((c)[3]) \
                 : "r"(a0), "r"(a1), "r"(a2), "r"(a3), "r"(b0), "r"(b1))

#define PF_L1(a) asm volatile("prefetch.global.L1 [%0];" :: "l"(a))
#define PF_L2(a) asm volatile("prefetch.global.L2 [%0];" :: "l"(a))

// ---------------- smem layout (bytes) ----------------
constexpr int ROWB    = 144;                  // 64 k *2B + 16B pad (ldmatrix conflict-free)
constexpr int OFF_BH  = 0;                    // hi: 256*144 = 36864
constexpr int OFF_BL  = 36864;                // lo: 36864
constexpr int SMEM_BYTES = 73728;             // 72KB -> 2 CTAs/SM
// epilogue overlay (BH/BL dead after last MMA):
constexpr int OFF_XSE  = 0;                   // 64*256*4 = 65536
constexpr int OFF_REDP = 65536;               // 64*17*4 = 4352
constexpr int OFF_RS   = OFF_REDP + 4352;     // 256
constexpr int OFF_S2   = OFF_RS + 256;        // 256
constexpr int OFF_RED  = OFF_S2 + 256;        // 256
constexpr int OFF_W8   = OFF_RED + 256;       // 8 warps x 5 vals = 160
constexpr int OFF_BC   = OFF_W8 + 160;        // 8   (total 70824 <= 73728)

// =====================================================================
// CTA = (b, p, q): rows [q*64, q*64+64), all 256 t-cols. 256 thr, 2 CTA/SM.
// =====================================================================
__global__ void __launch_bounds__(256, 2)
da_fused_kernel(const float* __restrict__ x, const float* __restrict__ w,
                const float* __restrict__ gamma, const float* __restrict__ beta,
                float* __restrict__ out)
{
    extern __shared__ __align__(16) char sm[];
    const uint32_t smb = smem_to_u32(sm);
    const int tid = threadIdx.x, wid = tid >> 5, lane = tid & 31;
    const int bx = blockIdx.x;                 // 0..31 = b*4 + q
    const int b = bx >> 2, q = bx & 3;
    const int p = blockIdx.y;
    const int m0 = q * 64;                     // global row base of this CTA
    const float* xbp = x + (size_t)(b * P_ + p) * (S_ * D_);

    // prefetch this CTA's W tile (64KB) into L2 for the epilogue fold
    {
        const float* wt = w + ((size_t)p << 16) + (size_t)m0 * 256 + (size_t)tid * 64;
        PF_L2(wt);
        PF_L2(wt + 32);
    }

    const int warp_m = wid >> 2;   // 0..1 : 32 m-rows
    const int warp_n = wid & 3;    // 0..3 : 64 n-cols

    // accumulators: 2 m-frags x 8 n-frags x 4 = 64 regs
    float acc[2][8][4];
    #pragma unroll
    for (int mi = 0; mi < 2; ++mi)
        #pragma unroll
        for (int nf = 0; nf < 8; ++nf)
            #pragma unroll
            for (int qq = 0; qq < 4; ++qq) acc[mi][nf][qq] = 0.f;

    // ldmatrix per-lane addressing (A reads the shared B tile at row offset m0)
    const uint32_t lrow = lane & 15;
    const uint32_t lcol = (lane >> 4) * 16;
    uint32_t aaddr[2], baddr[4];
    #pragma unroll
    for (int mi = 0; mi < 2; ++mi)
        aaddr[mi] = smb + OFF_BH + (uint32_t)(m0 + warp_m * 32 + mi * 16 + lrow) * ROWB + lcol;
    #pragma unroll
    for (int nj = 0; nj < 4; ++nj)
        baddr[nj] = smb + OFF_BH + (uint32_t)(warp_n * 64 + nj * 16 + lrow) * ROWB + lcol;

    const int rbase = tid >> 4;    // 0..15
    const int c4    = tid & 15;    // float4 col in 64-k chunk

    // ================= k-chunk loop (4 chunks of K=64) =================
    for (int kc = 0; kc < 4; ++kc) {
        __syncthreads();   // previous chunk's consumers done
        const float* xc = xbp + kc * 64 + c4 * 4;
        // two half-batches of 8 LDGs to keep MLP high and register peak low
        #pragma unroll
        for (int h = 0; h < 2; ++h) {
            float4 pv[8];
            #pragma unroll
            for (int j = 0; j < 8; ++j)
                pv[j] = __ldg(reinterpret_cast<const float4*>(
                    xc + (size_t)(rbase + 16 * (h * 8 + j)) * D_));
            #pragma unroll
            for (int j = 0; j < 8; ++j) {
                int row = rbase + 16 * (h * 8 + j);
                float4 v = pv[j];
                __nv_bfloat162 h01 = __floats2bfloat162_rn(v.x, v.y);
                __nv_bfloat162 h23 = __floats2bfloat162_rn(v.z, v.w);
                __nv_bfloat162 l01 = __floats2bfloat162_rn(v.x - __low2float(h01),
                                                           v.y - __high2float(h01));
                __nv_bfloat162 l23 = __floats2bfloat162_rn(v.z - __low2float(h23),
                                                           v.w - __high2float(h23));
                uint32_t off = (uint32_t)row * ROWB + (uint32_t)c4 * 8;
                *reinterpret_cast<uint2*>(sm + OFF_BH + off) =
                    make_uint2(*reinterpret_cast<uint32_t*>(&h01), *reinterpret_cast<uint32_t*>(&h23));
                *reinterpret_cast<uint2*>(sm + OFF_BL + off) =
                    make_uint2(*reinterpret_cast<uint32_t*>(&l01), *reinterpret_cast<uint32_t*>(&l23));
            }
        }
        __syncthreads();

        // prefetch next chunk into L1 (zero-register; lands during MMA below)
        if (kc < 3) {
            const float* xpf = xbp + (size_t)tid * 256 + (kc + 1) * 64;  // row=tid, next chunk
            PF_L1(xpf);
            PF_L1(xpf + 32);
        }

        #pragma unroll
        for (int ks = 0; ks < 4; ++ks) {
            const uint32_t ko = (uint32_t)ks * 32;
            uint32_t ah[2][4], al[2][4];
            #pragma unroll
            for (int mi = 0; mi < 2; ++mi) {
                LDSM4(ah[mi][0], ah[mi][1], ah[mi][2], ah[mi][3], aaddr[mi] + ko);
                LDSM4(al[mi][0], al[mi][1], al[mi][2], al[mi][3], aaddr[mi] + ko + 36864u);
            }
            #pragma unroll
            for (int nj = 0; nj < 4; ++nj) {
                uint32_t bh[4], bl[4];
                LDSM4(bh[0], bh[1], bh[2], bh[3], baddr[nj] + ko);
                LDSM4(bl[0], bl[1], bl[2], bl[3], baddr[nj] + ko + 36864u);
                #pragma unroll
                for (int nk = 0; nk < 2; ++nk) {
                    const int nf = nj * 2 + nk;
                    #pragma unroll
                    for (int mi = 0; mi < 2; ++mi) {
                        HMMA(acc[mi][nf], ah[mi][0], ah[mi][1], ah[mi][2], ah[mi][3],
                             bh[nk], bh[2 + nk]);                          // hi*hi
                        HMMA(acc[mi][nf], al[mi][0], al[mi][1], al[mi][2], al[mi][3],
                             bh[nk], bh[2 + nk]);                          // lo*hi
                        HMMA(acc[mi][nf], ah[mi][0], ah[mi][1], ah[mi][2], ah[mi][3],
                             bl[nk], bl[2 + nk]);                          // hi*lo
                    }
                }
            }
        }
    }
    __syncthreads();   // BH/BL dead -> overlay region usable

    // ================= fold W into per-row partials =================
    float* redp = reinterpret_cast<float*>(sm + OFF_REDP);
    const float* wp = w + ((size_t)p << 16);
    #pragma unroll
    for (int mi = 0; mi < 2; ++mi)
        #pragma unroll
        for (int half = 0; half < 2; ++half) {
            int rl = warp_m * 32 + mi * 16 + (lane >> 2) + half * 8;   // 0..63 local
            const float* wr = wp + (size_t)(m0 + rl) * 256 + warp_n * 64 + (lane & 3) * 2;
            float part = 0.f;
            #pragma unroll
            for (int nf = 0; nf < 8; ++nf) {
                float2 wv = __ldg(reinterpret_cast<const float2*>(wr + nf * 8));
                part = fmaf(acc[mi][nf][half * 2 + 0], wv.x, part);
                part = fmaf(acc[mi][nf][half * 2 + 1], wv.y, part);
            }
            redp[rl * 17 + warp_n * 4 + (lane & 3)] = part;
        }

    // ================= re-read own x rows into smem + row sums =================
    float* xs   = reinterpret_cast<float*>(sm + OFF_XSE);
    float* rssm = reinterpret_cast<float*>(sm + OFF_RS);
    float* s2sm = reinterpret_cast<float*>(sm + OFF_S2);
    #pragma unroll
    for (int j = 0; j < 8; ++j) {
        int r = wid * 8 + j;                       // 0..63 local
        const float* xr = xbp + (size_t)(m0 + r) * 256;
        float4 v0 = __ldg(reinterpret_cast<const float4*>(xr + lane * 4));
        float4 v1 = __ldg(reinterpret_cast<const float4*>(xr + 128 + lane * 4));
        *reinterpret_cast<float4*>(xs + r * 256 + lane * 4) = v0;
        *reinterpret_cast<float4*>(xs + r * 256 + 128 + lane * 4) = v1;
        float rsv = v0.x + v0.y + v0.z + v0.w + v1.x + v1.y + v1.z + v1.w;
        float s2v = v0.x * v0.x + v0.y * v0.y + v0.z * v0.z + v0.w * v0.w
                  + v1.x * v1.x + v1.y * v1.y + v1.z * v1.z + v1.w * v1.w;
        #pragma unroll
        for (int o = 16; o; o >>= 1) {
            rsv += __shfl_xor_sync(0xffffffffu, rsv, o);
            s2v += __shfl_xor_sync(0xffffffffu, s2v, o);
        }
        if (lane == 0) { rssm[r] = rsv; s2sm[r] = s2v; }
    }
    __syncthreads();

    // ================= finalize red + BN partials (single reduction pass) =================
    float* redsm = reinterpret_cast<float*>(sm + OFF_RED);
    float vals[5] = {0.f, 0.f, 0.f, 0.f, 0.f};
    if (tid < 64) {
        float rsum = 0.f;
        #pragma unroll
        for (int l = 0; l < 16; ++l) rsum += redp[tid * 17 + l];
        float red = rsum * 0.0625f;    // 1/sqrt(256)
        redsm[tid] = red;
        float xr = rssm[tid], x2 = s2sm[tid];
        vals[0] = xr; vals[1] = x2; vals[2] = red; vals[3] = red * red; vals[4] = red * xr;
    }
    float* w8 = reinterpret_cast<float*>(sm + OFF_W8);
    #pragma unroll
    for (int qq = 0; qq < 5; ++qq) {
        float v = vals[qq];
        #pragma unroll
        for (int o = 16; o; o >>= 1) v += __shfl_xor_sync(0xffffffffu, v, o);
        if (lane == 0) w8[wid * 5 + qq] = v;
    }
    __syncthreads();

    // ================= cross-CTA BN handshake (32 CTAs per channel) =================
    float* bc = reinterpret_cast<float*>(sm + OFF_BC);
    if (tid == 0) {
        int slot = (p * 32 + bx) * 5;
        #pragma unroll
        for (int qq = 0; qq < 5; ++qq) {
            float r = 0.f;
            for (int t = 0; t < 8; ++t) r += w8[t * 5 + qq];
            g_partials[slot + qq] = r;
        }
        __threadfence();
        int o = atomicAdd(&g_cnt[p], 1);
        if (o == 31) {
            __threadfence();
            float sx = 0.f, sx2 = 0.f, sr = 0.f, sr2 = 0.f, cr = 0.f;
            for (int c = 0; c < 32; ++c) {
                const float* qp = g_partials + (p * 32 + c) * 5;
                sx += qp[0]; sx2 += qp[1]; sr += qp[2]; sr2 += qp[3]; cr += qp[4];
            }
            const float N = (float)(B_ * S_ * D_);
            float sumy  = sx + (float)D_ * sr;
            float sumy2 = sx2 + 2.f * cr + (float)D_ * sr2;
            float mean = sumy / N;
            float var  = sumy2 / N - mean * mean;
            float sc = __ldg(gamma + p) * rsqrtf(var + 1e-5f);
            g_scale[p] = sc;
            g_bias[p]  = __ldg(beta + p) - mean * sc;
            __threadfence();
            atomicExch(&g_flag[p], 1);
        }
        volatile int* fl = (volatile int*)&g_flag[p];
        while (*fl == 0) __nanosleep(64);
        __threadfence();
        bc[0] = g_scale[p];
        bc[1] = g_bias[p];
        int o2 = atomicAdd(&g_cnt2[p], 1);
        if (o2 == 31) {        // all consumers done: reset for next graph replay
            g_flag[p] = 0; g_cnt[p] = 0; g_cnt2[p] = 0;
        }
    }
    __syncthreads();
    const float sc = bc[0], bi = bc[1];

    // ================= output: out = (x + red) * sc + bi =================
    float* ob = out + ((size_t)(b * P_ + p) << 16) + (size_t)m0 * 256;
    #pragma unroll
    for (int j = 0; j < 8; ++j) {
        int r = wid * 8 + j;
        float red = redsm[r];
        #pragma unroll
        for (int it = 0; it < 2; ++it) {
            float4 v = *reinterpret_cast<const float4*>(xs + r * 256 + it * 128 + lane * 4);
            v.x = fmaf(v.x + red, sc, bi);
            v.y = fmaf(v.y + red, sc, bi);
            v.z = fmaf(v.z + red, sc, bi);
            v.w = fmaf(v.w + red, sc, bi);
            *reinterpret_cast<float4*>(ob + (size_t)r * 256 + it * 128 + lane * 4) = v;
        }
    }
}

// =====================================================================
extern "C" void kernel_launch(void* const* d_in, const int* in_sizes, int n_in,
                              void* d_out, int out_size)
{
    const float* x     = (const float*)d_in[0];
    const float* w     = (const float*)d_in[1];
    const float* gamma = (const float*)d_in[2];
    const float* beta  = (const float*)d_in[3];
    float* out = (float*)d_out;

    cudaFuncSetAttribute(da_fused_kernel,
                         cudaFuncAttributeMaxDynamicSharedMemorySize, SMEM_BYTES);

    dim3 grid(32, P_);   // blockIdx.x = b*4+q (channel CTAs contiguous), blockIdx.y = p
    da_fused_kernel<<<grid, 256, SMEM_BYTES>>>(x, w, gamma, beta, out);
}

// round 11
// speedup vs baseline: 1.9023x; 1.3664x over previous
#include <cuda_runtime.h>
#include <cuda_bf16.h>
#include <cstdint>

#define B_ 8
#define P_ 64
#define S_ 256
#define D_ 256

// ---------------- device scratch (zero-init at load; reset each run) ----------------
__device__ float g_partials[P_ * 32 * 5];
__device__ float g_scale[P_];
__device__ float g_bias[P_];
__device__ int   g_cnt[P_];
__device__ int   g_cnt2[P_];
__device__ int   g_flag[P_];

__device__ __forceinline__ uint32_t smem_to_u32(const void* p) {
    uint32_t a;
    asm("{ .reg .u64 t; cvta.to.shared.u64 t, %1; cvt.u32.u64 %0, t; }" : "=r"(a) : "l"(p));
    return a;
}

#define LDSM4(d0, d1, d2, d3, a) \
    asm volatile("ldmatrix.sync.aligned.m8n8.x4.shared.b16 {%0,%1,%2,%3}, [%4];" \
                 : "=r"(d0), "=r"(d1), "=r"(d2), "=r"(d3) : "r"(a))

#define HMMA(c, a0, a1, a2, a3, b0, b1) \
    asm volatile("mma.sync.aligned.m16n8k16.row.col.f32.bf16.bf16.f32 " \
                 "{%0,%1,%2,%3}, {%4,%5,%6,%7}, {%8,%9}, {%0,%1,%2,%3};" \
                 : "+f"((c)[0]), "+f"((c)[1]), "+f"((c)[2]), "+f"((c)[3]) \
                 : "r"(a0), "r"(a1), "r"(a2), "r"(a3), "r"(b0), "r"(b1))

#define PF_L1(a) asm volatile("prefetch.global.L1 [%0];" :: "l"(a))
#define PF_L2(a) asm volatile("prefetch.global.L2 [%0];" :: "l"(a))

// ---------------- smem layout (bytes) ----------------
constexpr int ROWB    = 144;                  // 64 k *2B + 16B pad (ldmatrix conflict-free)
constexpr int OFF_BH  = 0;                    // hi: 256*144 = 36864 (single-pass: no lo)
constexpr int SMEM_BYTES = 73728;             // 72KB -> 2 CTAs/SM (epilogue overlay needs 71KB)
// epilogue overlay (BH dead after last MMA):
constexpr int OFF_XSE  = 0;                   // 64*256*4 = 65536
constexpr int OFF_REDP = 65536;               // 64*17*4 = 4352
constexpr int OFF_RS   = OFF_REDP + 4352;     // 256
constexpr int OFF_S2   = OFF_RS + 256;        // 256
constexpr int OFF_RED  = OFF_S2 + 256;        // 256
constexpr int OFF_W8   = OFF_RED + 256;       // 8 warps x 5 vals = 160
constexpr int OFF_BC   = OFF_W8 + 160;        // 8   (total 70824 <= 73728)

// =====================================================================
// CTA = (b, p, q): rows [q*64, q*64+64), all 256 t-cols. 256 thr, 2 CTA/SM.
// Single-pass bf16 Gram GEMM (error ~2e-4 rel, threshold 1e-3).
// =====================================================================
__global__ void __launch_bounds__(256, 2)
da_fused_kernel(const float* __restrict__ x, const float* __restrict__ w,
                const float* __restrict__ gamma, const float* __restrict__ beta,
                float* __restrict__ out)
{
    extern __shared__ __align__(16) char sm[];
    const uint32_t smb = smem_to_u32(sm);
    const int tid = threadIdx.x, wid = tid >> 5, lane = tid & 31;
    const int bx = blockIdx.x;                 // 0..31 = b*4 + q
    const int b = bx >> 2, q = bx & 3;
    const int p = blockIdx.y;
    const int m0 = q * 64;                     // global row base of this CTA
    const float* xbp = x + (size_t)(b * P_ + p) * (S_ * D_);

    // prefetch this CTA's W tile (64KB) into L2 for the epilogue fold
    {
        const float* wt = w + ((size_t)p << 16) + (size_t)m0 * 256 + (size_t)tid * 64;
        PF_L2(wt);
        PF_L2(wt + 32);
    }

    const int warp_m = wid >> 2;   // 0..1 : 32 m-rows
    const int warp_n = wid & 3;    // 0..3 : 64 n-cols

    // accumulators: 2 m-frags x 8 n-frags x 4 = 64 regs
    float acc[2][8][4];
    #pragma unroll
    for (int mi = 0; mi < 2; ++mi)
        #pragma unroll
        for (int nf = 0; nf < 8; ++nf)
            #pragma unroll
            for (int qq = 0; qq < 4; ++qq) acc[mi][nf][qq] = 0.f;

    // ldmatrix per-lane addressing (A reads the shared tile at row offset m0)
    const uint32_t lrow = lane & 15;
    const uint32_t lcol = (lane >> 4) * 16;
    uint32_t aaddr[2], baddr[4];
    #pragma unroll
    for (int mi = 0; mi < 2; ++mi)
        aaddr[mi] = smb + OFF_BH + (uint32_t)(m0 + warp_m * 32 + mi * 16 + lrow) * ROWB + lcol;
    #pragma unroll
    for (int nj = 0; nj < 4; ++nj)
        baddr[nj] = smb + OFF_BH + (uint32_t)(warp_n * 64 + nj * 16 + lrow) * ROWB + lcol;

    const int rbase = tid >> 4;    // 0..15
    const int c4    = tid & 15;    // float4 col in 64-k chunk

    // ================= k-chunk loop (4 chunks of K=64) =================
    for (int kc = 0; kc < 4; ++kc) {
        __syncthreads();   // previous chunk's consumers done
        const float* xc = xbp + kc * 64 + c4 * 4;
        // two half-batches of 8 LDGs to keep MLP high and register peak low
        #pragma unroll
        for (int h = 0; h < 2; ++h) {
            float4 pv[8];
            #pragma unroll
            for (int j = 0; j < 8; ++j)
                pv[j] = __ldg(reinterpret_cast<const float4*>(
                    xc + (size_t)(rbase + 16 * (h * 8 + j)) * D_));
            #pragma unroll
            for (int j = 0; j < 8; ++j) {
                int row = rbase + 16 * (h * 8 + j);
                float4 v = pv[j];
                __nv_bfloat162 h01 = __floats2bfloat162_rn(v.x, v.y);
                __nv_bfloat162 h23 = __floats2bfloat162_rn(v.z, v.w);
                uint32_t off = (uint32_t)row * ROWB + (uint32_t)c4 * 8;
                *reinterpret_cast<uint2*>(sm + OFF_BH + off) =
                    make_uint2(*reinterpret_cast<uint32_t*>(&h01), *reinterpret_cast<uint32_t*>(&h23));
            }
        }
        __syncthreads();

        // prefetch next chunk into L1 (zero-register; lands during MMA below)
        if (kc < 3) {
            const float* xpf = xbp + (size_t)tid * 256 + (kc + 1) * 64;  // row=tid, next chunk
            PF_L1(xpf);
            PF_L1(xpf + 32);
        }

        #pragma unroll
        for (int ks = 0; ks < 4; ++ks) {
            const uint32_t ko = (uint32_t)ks * 32;
            uint32_t ah[2][4];
            #pragma unroll
            for (int mi = 0; mi < 2; ++mi)
                LDSM4(ah[mi][0], ah[mi][1], ah[mi][2], ah[mi][3], aaddr[mi] + ko);
            #pragma unroll
            for (int nj = 0; nj < 4; ++nj) {
                uint32_t bh[4];
                LDSM4(bh[0], bh[1], bh[2], bh[3], baddr[nj] + ko);
                #pragma unroll
                for (int nk = 0; nk < 2; ++nk) {
                    const int nf = nj * 2 + nk;
                    #pragma unroll
                    for (int mi = 0; mi < 2; ++mi)
                        HMMA(acc[mi][nf], ah[mi][0], ah[mi][1], ah[mi][2], ah[mi][3],
                             bh[nk], bh[2 + nk]);
                }
            }
        }
    }
    __syncthreads();   // BH dead -> overlay region usable

    // ================= fold W into per-row partials =================
    float* redp = reinterpret_cast<float*>(sm + OFF_REDP);
    const float* wp = w + ((size_t)p << 16);
    #pragma unroll
    for (int mi = 0; mi < 2; ++mi)
        #pragma unroll
        for (int half = 0; half < 2; ++half) {
            int rl = warp_m * 32 + mi * 16 + (lane >> 2) + half * 8;   // 0..63 local
            const float* wr = wp + (size_t)(m0 + rl) * 256 + warp_n * 64 + (lane & 3) * 2;
            float part = 0.f;
            #pragma unroll
            for (int nf = 0; nf < 8; ++nf) {
                float2 wv = __ldg(reinterpret_cast<const float2*>(wr + nf * 8));
                part = fmaf(acc[mi][nf][half * 2 + 0], wv.x, part);
                part = fmaf(acc[mi][nf][half * 2 + 1], wv.y, part);
            }
            redp[rl * 17 + warp_n * 4 + (lane & 3)] = part;
        }

    // ================= re-read own x rows into smem + row sums =================
    float* xs   = reinterpret_cast<float*>(sm + OFF_XSE);
    float* rssm = reinterpret_cast<float*>(sm + OFF_RS);
    float* s2sm = reinterpret_cast<float*>(sm + OFF_S2);
    #pragma unroll
    for (int j = 0; j < 8; ++j) {
        int r = wid * 8 + j;                       // 0..63 local
        const float* xr = xbp + (size_t)(m0 + r) * 256;
        float4 v0 = __ldg(reinterpret_cast<const float4*>(xr + lane * 4));
        float4 v1 = __ldg(reinterpret_cast<const float4*>(xr + 128 + lane * 4));
        *reinterpret_cast<float4*>(xs + r * 256 + lane * 4) = v0;
        *reinterpret_cast<float4*>(xs + r * 256 + 128 + lane * 4) = v1;
        float rsv = v0.x + v0.y + v0.z + v0.w + v1.x + v1.y + v1.z + v1.w;
        float s2v = v0.x * v0.x + v0.y * v0.y + v0.z * v0.z + v0.w * v0.w
                  + v1.x * v1.x + v1.y * v1.y + v1.z * v1.z + v1.w * v1.w;
        #pragma unroll
        for (int o = 16; o; o >>= 1) {
            rsv += __shfl_xor_sync(0xffffffffu, rsv, o);
            s2v += __shfl_xor_sync(0xffffffffu, s2v, o);
        }
        if (lane == 0) { rssm[r] = rsv; s2sm[r] = s2v; }
    }
    __syncthreads();

    // ================= finalize red + BN partials (single reduction pass) =================
    float* redsm = reinterpret_cast<float*>(sm + OFF_RED);
    float vals[5] = {0.f, 0.f, 0.f, 0.f, 0.f};
    if (tid < 64) {
        float rsum = 0.f;
        #pragma unroll
        for (int l = 0; l < 16; ++l) rsum += redp[tid * 17 + l];
        float red = rsum * 0.0625f;    // 1/sqrt(256)
        redsm[tid] = red;
        float xr = rssm[tid], x2 = s2sm[tid];
        vals[0] = xr; vals[1] = x2; vals[2] = red; vals[3] = red * red; vals[4] = red * xr;
    }
    float* w8 = reinterpret_cast<float*>(sm + OFF_W8);
    #pragma unroll
    for (int qq = 0; qq < 5; ++qq) {
        float v = vals[qq];
        #pragma unroll
        for (int o = 16; o; o >>= 1) v += __shfl_xor_sync(0xffffffffu, v, o);
        if (lane == 0) w8[wid * 5 + qq] = v;
    }
    __syncthreads();

    // ================= cross-CTA BN handshake (32 CTAs per channel) =================
    float* bc = reinterpret_cast<float*>(sm + OFF_BC);
    if (tid == 0) {
        int slot = (p * 32 + bx) * 5;
        #pragma unroll
        for (int qq = 0; qq < 5; ++qq) {
            float r = 0.f;
            for (int t = 0; t < 8; ++t) r += w8[t * 5 + qq];
            g_partials[slot + qq] = r;
        }
        __threadfence();
        int o = atomicAdd(&g_cnt[p], 1);
        if (o == 31) {
            __threadfence();
            float sx = 0.f, sx2 = 0.f, sr = 0.f, sr2 = 0.f, cr = 0.f;
            for (int c = 0; c < 32; ++c) {
                const float* qp = g_partials + (p * 32 + c) * 5;
                sx += qp[0]; sx2 += qp[1]; sr += qp[2]; sr2 += qp[3]; cr += qp[4];
            }
            const float N = (float)(B_ * S_ * D_);
            float sumy  = sx + (float)D_ * sr;
            float sumy2 = sx2 + 2.f * cr + (float)D_ * sr2;
            float mean = sumy / N;
            float var  = sumy2 / N - mean * mean;
            float sc = __ldg(gamma + p) * rsqrtf(var + 1e-5f);
            g_scale[p] = sc;
            g_bias[p]  = __ldg(beta + p) - mean * sc;
            __threadfence();
            atomicExch(&g_flag[p], 1);
        }
        volatile int* fl = (volatile int*)&g_flag[p];
        while (*fl == 0) __nanosleep(64);
        __threadfence();
        bc[0] = g_scale[p];
        bc[1] = g_bias[p];
        int o2 = atomicAdd(&g_cnt2[p], 1);
        if (o2 == 31) {        // all consumers done: reset for next graph replay
            g_flag[p] = 0; g_cnt[p] = 0; g_cnt2[p] = 0;
        }
    }
    __syncthreads();
    const float sc = bc[0], bi = bc[1];

    // ================= output: out = (x + red) * sc + bi =================
    float* ob = out + ((size_t)(b * P_ + p) << 16) + (size_t)m0 * 256;
    #pragma unroll
    for (int j = 0; j < 8; ++j) {
        int r = wid * 8 + j;
        float red = redsm[r];
        #pragma unroll
        for (int it = 0; it < 2; ++it) {
            float4 v = *reinterpret_cast<const float4*>(xs + r * 256 + it * 128 + lane * 4);
            v.x = fmaf(v.x + red, sc, bi);
            v.y = fmaf(v.y + red, sc, bi);
            v.z = fmaf(v.z + red, sc, bi);
            v.w = fmaf(v.w + red, sc, bi);
            *reinterpret_cast<float4*>(ob + (size_t)r * 256 + it * 128 + lane * 4) = v;
        }
    }
}

// =====================================================================
extern "C" void kernel_launch(void* const* d_in, const int* in_sizes, int n_in,
                              void* d_out, int out_size)
{
    const float* x     = (const float*)d_in[0];
    const float* w     = (const float*)d_in[1];
    const float* gamma = (const float*)d_in[2];
    const float* beta  = (const float*)d_in[3];
    float* out = (float*)d_out;

    cudaFuncSetAttribute(da_fused_kernel,
                         cudaFuncAttributeMaxDynamicSharedMemorySize, SMEM_BYTES);

    dim3 grid(32, P_);   // blockIdx.x = b*4+q (channel CTAs contiguous), blockIdx.y = p
    da_fused_kernel<<<grid, 256, SMEM_BYTES>>>(x, w, gamma, beta, out);
}

// round 12
// speedup vs baseline: 1.9948x; 1.0487x over previous
#include <cuda_runtime.h>
#include <cuda_bf16.h>
#include <cstdint>

#define B_ 8
#define P_ 64
#define S_ 256
#define D_ 256

// ---------------- device scratch (zero-init at load; reset each run) ----------------
__device__ float g_partials[P_ * 32 * 5];
__device__ float g_redhalf[2048 * 64];     // per-(p,b,q) pair: follower's partial red
__device__ int   g_pflag[2048];
__device__ float g_scale[P_];
__device__ float g_bias[P_];
__device__ int   g_cnt[P_];
__device__ int   g_cnt2[P_];
__device__ int   g_flag[P_];

__device__ __forceinline__ uint32_t smem_to_u32(const void* p) {
    uint32_t a;
    asm("{ .reg .u64 t; cvta.to.shared.u64 t, %1; cvt.u32.u64 %0, t; }" : "=r"(a) : "l"(p));
    return a;
}

#define LDSM4(d0, d1, d2, d3, a) \
    asm volatile("ldmatrix.sync.aligned.m8n8.x4.shared.b16 {%0,%1,%2,%3}, [%4];" \
                 : "=r"(d0), "=r"(d1), "=r"(d2), "=r"(d3) : "r"(a))

#define HMMA(c, a0, a1, a2, a3, b0, b1) \
    asm volatile("mma.sync.aligned.m16n8k16.row.col.f32.bf16.bf16.f32 " \
                 "{%0,%1,%2,%3}, {%4,%5,%6,%7}, {%8,%9}, {%0,%1,%2,%3};" \
                 : "+f"((c)[0]), "+f"((c)[1]), "+f"((c)[2]), "+f"((c)[3]) \
                 : "r"(a0), "r"(a1), "r"(a2), "r"(a3), "r"(b0), "r"(b1))

#define PF_L2(a) asm volatile("prefetch.global.L2 [%0];" :: "l"(a))

// ---------------- smem layout (bytes) ----------------
constexpr int ROWB   = 144;                 // 64 k *2B + 16B pad (ldmatrix conflict-free)
constexpr int OFF_A  = 128 * ROWB;          // A region (when disjoint): 18432
constexpr int SMEM_BYTES = OFF_A + 64 * ROWB;   // 27648 -> 3 CTAs/SM (regs permitting)
// epilogue overlay (buffer dead after last MMA):
constexpr int OFF_REDP = 0;                 // 64*17*4 = 4352
constexpr int OFF_RS   = 4352;              // 256
constexpr int OFF_S2   = 4608;              // 256
constexpr int OFF_RED  = 4864;              // 256
constexpr int OFF_W8   = 5120;              // 160
constexpr int OFF_BC   = 5280;              // 8

// =====================================================================
// CTA = (b, p, q, nh): rows [q*64,+64) x t-cols [nh*128,+128).
// 256 thr, 3 CTA/SM. nh=1 (follower) contributes partial red and exits;
// nh=0 (leader) merges, does BN handshake + output.
// =====================================================================
__global__ void __launch_bounds__(256, 3)
da_fused_kernel(const float* __restrict__ x, const float* __restrict__ w,
                const float* __restrict__ gamma, const float* __restrict__ beta,
                float* __restrict__ out)
{
    extern __shared__ __align__(16) char sm[];
    const uint32_t smb = smem_to_u32(sm);
    const int tid = threadIdx.x, wid = tid >> 5, lane = tid & 31;
    const int bx = blockIdx.x;                 // 0..63 = b*8 + q*2 + nh
    const int nh = bx & 1, q = (bx >> 1) & 3, b = bx >> 3;
    const int p = blockIdx.y;
    const int m0 = q * 64;                     // global row base
    const int nb0 = nh * 128;                  // global t-col base
    const int pair = ((p * 8 + b) * 4 + q);
    const float* xbp = x + (size_t)(b * P_ + p) * (S_ * D_);
    const float* wp  = w + ((size_t)p << 16);

    // prefetch this CTA's W half-tile (32KB) into L2
    {
        const float* wt = wp + (size_t)(m0 + (tid >> 2)) * 256 + nb0 + (tid & 3) * 32;
        PF_L2(wt);
    }

    const int warp_m = wid >> 2;   // 0..1 : 32 m-rows
    const int warp_n = wid & 3;    // 0..3 : 32 n-cols

    // accumulators: 2 m-frags x 4 n-frags x 4 = 32 regs
    float acc[2][4][4];
    #pragma unroll
    for (int mi = 0; mi < 2; ++mi)
        #pragma unroll
        for (int nf = 0; nf < 4; ++nf)
            #pragma unroll
            for (int qq = 0; qq < 4; ++qq) acc[mi][nf][qq] = 0.f;

    const bool contained = ((q >> 1) == nh);   // A rows inside B slice?
    const uint32_t aBase = contained ? smb + (uint32_t)(m0 - nb0) * ROWB
                                     : smb + OFF_A;

    const uint32_t lrow = lane & 15;
    const uint32_t lcol = (lane >> 4) * 16;
    uint32_t aaddr[2], baddr[2];
    #pragma unroll
    for (int mi = 0; mi < 2; ++mi)
        aaddr[mi] = aBase + (uint32_t)(warp_m * 32 + mi * 16 + lrow) * ROWB + lcol;
    #pragma unroll
    for (int nj = 0; nj < 2; ++nj)
        baddr[nj] = smb + (uint32_t)(warp_n * 32 + nj * 16 + lrow) * ROWB + lcol;

    const int rbase = tid >> 4;    // 0..15
    const int c4    = tid & 15;    // float4 col within 64-k chunk

    // ================= k-chunk loop (4 chunks of K=64) =================
    for (int kc = 0; kc < 4; ++kc) {
        __syncthreads();
        // ---- B slice: 128 rows ----
        {
            float4 pv[8];
            #pragma unroll
            for (int j = 0; j < 8; ++j)
                pv[j] = __ldg(reinterpret_cast<const float4*>(
                    xbp + (size_t)(nb0 + rbase + 16 * j) * D_ + kc * 64 + c4 * 4));
            #pragma unroll
            for (int j = 0; j < 8; ++j) {
                float4 v = pv[j];
                __nv_bfloat162 h01 = __floats2bfloat162_rn(v.x, v.y);
                __nv_bfloat162 h23 = __floats2bfloat162_rn(v.z, v.w);
                *reinterpret_cast<uint2*>(sm + (size_t)(rbase + 16 * j) * ROWB + c4 * 8) =
                    make_uint2(*reinterpret_cast<uint32_t*>(&h01),
                               *reinterpret_cast<uint32_t*>(&h23));
            }
        }
        // ---- A slice (64 rows) when disjoint ----
        if (!contained) {
            float4 pv[4];
            #pragma unroll
            for (int j = 0; j < 4; ++j)
                pv[j] = __ldg(reinterpret_cast<const float4*>(
                    xbp + (size_t)(m0 + rbase + 16 * j) * D_ + kc * 64 + c4 * 4));
            #pragma unroll
            for (int j = 0; j < 4; ++j) {
                float4 v = pv[j];
                __nv_bfloat162 h01 = __floats2bfloat162_rn(v.x, v.y);
                __nv_bfloat162 h23 = __floats2bfloat162_rn(v.z, v.w);
                *reinterpret_cast<uint2*>(sm + OFF_A + (size_t)(rbase + 16 * j) * ROWB + c4 * 8) =
                    make_uint2(*reinterpret_cast<uint32_t*>(&h01),
                               *reinterpret_cast<uint32_t*>(&h23));
            }
        }
        __syncthreads();

        #pragma unroll
        for (int ks = 0; ks < 4; ++ks) {
            const uint32_t ko = (uint32_t)ks * 32;
            uint32_t ah[2][4], bh[2][4];
            #pragma unroll
            for (int mi = 0; mi < 2; ++mi)
                LDSM4(ah[mi][0], ah[mi][1], ah[mi][2], ah[mi][3], aaddr[mi] + ko);
            #pragma unroll
            for (int nj = 0; nj < 2; ++nj)
                LDSM4(bh[nj][0], bh[nj][1], bh[nj][2], bh[nj][3], baddr[nj] + ko);
            #pragma unroll
            for (int nj = 0; nj < 2; ++nj)
                #pragma unroll
                for (int nk = 0; nk < 2; ++nk) {
                    const int nf = nj * 2 + nk;
                    #pragma unroll
                    for (int mi = 0; mi < 2; ++mi)
                        HMMA(acc[mi][nf], ah[mi][0], ah[mi][1], ah[mi][2], ah[mi][3],
                             bh[nj][nk], bh[nj][2 + nk]);
                }
        }
    }
    __syncthreads();   // buffer dead -> overlay usable

    // ================= fold W (own n-half) into per-row partials =================
    float* redp = reinterpret_cast<float*>(sm + OFF_REDP);
    #pragma unroll
    for (int mi = 0; mi < 2; ++mi)
        #pragma unroll
        for (int half = 0; half < 2; ++half) {
            int rl = warp_m * 32 + mi * 16 + (lane >> 2) + half * 8;   // 0..63 local
            const float* wr = wp + (size_t)(m0 + rl) * 256 + nb0 + warp_n * 32 + (lane & 3) * 2;
            float part = 0.f;
            #pragma unroll
            for (int nf = 0; nf < 4; ++nf) {
                float2 wv = __ldg(reinterpret_cast<const float2*>(
                    wr + (nf >> 1) * 16 + (nf & 1) * 8));
                part = fmaf(acc[mi][nf][half * 2 + 0], wv.x, part);
                part = fmaf(acc[mi][nf][half * 2 + 1], wv.y, part);
            }
            redp[rl * 17 + warp_n * 4 + (lane & 3)] = part;
        }
    __syncthreads();

    // reduce 16 partials per row -> this CTA's (unscaled) half-red
    float rsum = 0.f;
    if (tid < 64) {
        #pragma unroll
        for (int l = 0; l < 16; ++l) rsum += redp[tid * 17 + l];
    }

    // ================= follower: publish half-red and exit =================
    if (nh == 1) {
        if (tid < 64) {
            g_redhalf[pair * 64 + tid] = rsum;
            __threadfence();
        }
        __syncthreads();
        if (tid == 0) atomicExch(&g_pflag[pair], 1);
        return;
    }

    // ================= leader: row sums of x (direct from global) =================
    float* rssm = reinterpret_cast<float*>(sm + OFF_RS);
    float* s2sm = reinterpret_cast<float*>(sm + OFF_S2);
    #pragma unroll
    for (int j = 0; j < 8; ++j) {
        int r = wid * 8 + j;                       // 0..63 local
        const float* xr = xbp + (size_t)(m0 + r) * 256;
        float4 v0 = __ldg(reinterpret_cast<const float4*>(xr + lane * 4));
        float4 v1 = __ldg(reinterpret_cast<const float4*>(xr + 128 + lane * 4));
        float rsv = v0.x + v0.y + v0.z + v0.w + v1.x + v1.y + v1.z + v1.w;
        float s2v = v0.x * v0.x + v0.y * v0.y + v0.z * v0.z + v0.w * v0.w
                  + v1.x * v1.x + v1.y * v1.y + v1.z * v1.z + v1.w * v1.w;
        #pragma unroll
        for (int o = 16; o; o >>= 1) {
            rsv += __shfl_xor_sync(0xffffffffu, rsv, o);
            s2v += __shfl_xor_sync(0xffffffffu, s2v, o);
        }
        if (lane == 0) { rssm[r] = rsv; s2sm[r] = s2v; }
    }

    // wait for sibling's half-red
    if (tid == 0) {
        volatile int* fl = (volatile int*)&g_pflag[pair];
        while (*fl == 0) __nanosleep(32);
        __threadfence();
    }
    __syncthreads();

    // ================= merge red + BN vals =================
    float* redsm = reinterpret_cast<float*>(sm + OFF_RED);
    float vals[5] = {0.f, 0.f, 0.f, 0.f, 0.f};
    if (tid < 64) {
        float sib = g_redhalf[pair * 64 + tid];
        float red = (rsum + sib) * 0.0625f;     // 1/sqrt(256)
        redsm[tid] = red;
        float xr = rssm[tid], x2 = s2sm[tid];
        vals[0] = xr; vals[1] = x2; vals[2] = red; vals[3] = red * red; vals[4] = red * xr;
    }
    float* w8 = reinterpret_cast<float*>(sm + OFF_W8);
    #pragma unroll
    for (int qq = 0; qq < 5; ++qq) {
        float v = vals[qq];
        #pragma unroll
        for (int o = 16; o; o >>= 1) v += __shfl_xor_sync(0xffffffffu, v, o);
        if (lane == 0) w8[wid * 5 + qq] = v;
    }
    __syncthreads();
    if (tid == 32) g_pflag[pair] = 0;          // reset for next graph replay

    // ================= cross-CTA BN handshake (32 leaders per channel) =================
    float* bc = reinterpret_cast<float*>(sm + OFF_BC);
    if (tid == 0) {
        int slot = (p * 32 + b * 4 + q) * 5;
        #pragma unroll
        for (int qq = 0; qq < 5; ++qq) {
            float r = 0.f;
            for (int t = 0; t < 8; ++t) r += w8[t * 5 + qq];
            g_partials[slot + qq] = r;
        }
        __threadfence();
        int o = atomicAdd(&g_cnt[p], 1);
        if (o == 31) {
            __threadfence();
            float sx = 0.f, sx2 = 0.f, sr = 0.f, sr2 = 0.f, cr = 0.f;
            for (int c = 0; c < 32; ++c) {
                const float* qp = g_partials + (p * 32 + c) * 5;
                sx += qp[0]; sx2 += qp[1]; sr += qp[2]; sr2 += qp[3]; cr += qp[4];
            }
            const float N = (float)(B_ * S_ * D_);
            float sumy  = sx + (float)D_ * sr;
            float sumy2 = sx2 + 2.f * cr + (float)D_ * sr2;
            float mean = sumy / N;
            float var  = sumy2 / N - mean * mean;
            float sc = __ldg(gamma + p) * rsqrtf(var + 1e-5f);
            g_scale[p] = sc;
            g_bias[p]  = __ldg(beta + p) - mean * sc;
            __threadfence();
            atomicExch(&g_flag[p], 1);
        }
        volatile int* fl = (volatile int*)&g_flag[p];
        while (*fl == 0) __nanosleep(64);
        __threadfence();
        bc[0] = g_scale[p];
        bc[1] = g_bias[p];
        int o2 = atomicAdd(&g_cnt2[p], 1);
        if (o2 == 31) {        // all consumers done: reset for next graph replay
            g_flag[p] = 0; g_cnt[p] = 0; g_cnt2[p] = 0;
        }
    }
    __syncthreads();
    const float sc = bc[0], bi = bc[1];

    // ================= output: out = (x + red) * sc + bi (x direct from L2) =================
    float* ob = out + ((size_t)(b * P_ + p) << 16) + (size_t)m0 * 256;
    #pragma unroll
    for (int j = 0; j < 8; ++j) {
        int r = wid * 8 + j;
        float red = redsm[r];
        const float* xr = xbp + (size_t)(m0 + r) * 256;
        #pragma unroll
        for (int it = 0; it < 2; ++it) {
            float4 v = __ldg(reinterpret_cast<const float4*>(xr + it * 128 + lane * 4));
            v.x = fmaf(v.x + red, sc, bi);
            v.y = fmaf(v.y + red, sc, bi);
            v.z = fmaf(v.z + red, sc, bi);
            v.w = fmaf(v.w + red, sc, bi);
            *reinterpret_cast<float4*>(ob + (size_t)r * 256 + it * 128 + lane * 4) = v;
        }
    }
}

// =====================================================================
extern "C" void kernel_launch(void* const* d_in, const int* in_sizes, int n_in,
                              void* d_out, int out_size)
{
    const float* x     = (const float*)d_in[0];
    const float* w     = (const float*)d_in[1];
    const float* gamma = (const float*)d_in[2];
    const float* beta  = (const float*)d_in[3];
    float* out = (float*)d_out;

    cudaFuncSetAttribute(da_fused_kernel,
                         cudaFuncAttributeMaxDynamicSharedMemorySize, SMEM_BYTES);

    dim3 grid(64, P_);   // blockIdx.x = b*8+q*2+nh (pairs adjacent, channels contiguous)
    da_fused_kernel<<<grid, 256, SMEM_BYTES>>>(x, w, gamma, beta, out);
}

// round 13
// speedup vs baseline: 2.1598x; 1.0827x over previous
#include <cuda_runtime.h>
#include <cuda_bf16.h>
#include <cstdint>

#define B_ 8
#define P_ 64
#define S_ 256
#define D_ 256

// ---------------- device scratch (zero-init at load; reset each run) ----------------
__device__ float g_partials[P_ * 32 * 5];
__device__ float g_redhalf[2048 * 64];     // per-(p,b,q) pair: follower's partial red
__device__ int   g_pflag[2048];
__device__ float g_scale[P_];
__device__ float g_bias[P_];
__device__ int   g_cnt[P_];
__device__ int   g_cnt2[P_];
__device__ int   g_flag[P_];

__device__ __forceinline__ uint32_t smem_to_u32(const void* p) {
    uint32_t a;
    asm("{ .reg .u64 t; cvta.to.shared.u64 t, %1; cvt.u32.u64 %0, t; }" : "=r"(a) : "l"(p));
    return a;
}

#define LDSM4(d0, d1, d2, d3, a) \
    asm volatile("ldmatrix.sync.aligned.m8n8.x4.shared.b16 {%0,%1,%2,%3}, [%4];" \
                 : "=r"(d0), "=r"(d1), "=r"(d2), "=r"(d3) : "r"(a))

#define HMMA(c, a0, a1, a2, a3, b0, b1) \
    asm volatile("mma.sync.aligned.m16n8k16.row.col.f32.bf16.bf16.f32 " \
                 "{%0,%1,%2,%3}, {%4,%5,%6,%7}, {%8,%9}, {%0,%1,%2,%3};" \
                 : "+f"((c)[0]), "+f"((c)[1]), "+f"((c)[2]), "+f"((c)[3]) \
                 : "r"(a0), "r"(a1), "r"(a2), "r"(a3), "r"(b0), "r"(b1))

#define PF_L2(a) asm volatile("prefetch.global.L2 [%0];" :: "l"(a))

// ---------------- smem layout (bytes) ----------------
constexpr int ROWB   = 144;                 // 64 k *2B + 16B pad (ldmatrix conflict-free)
constexpr int OFF_A  = 128 * ROWB;          // A region (when disjoint): 18432
constexpr int SMEM_BYTES = OFF_A + 64 * ROWB;   // 27648 -> 4 CTAs/SM (regs permitting)
// epilogue overlay (buffer dead after last MMA):
constexpr int OFF_REDP = 0;                 // 64*17*4 = 4352
constexpr int OFF_RS   = 4352;              // 256
constexpr int OFF_S2   = 4608;              // 256
constexpr int OFF_RED  = 4864;              // 256
constexpr int OFF_W8   = 5120;              // 160
constexpr int OFF_BC   = 5280;              // 8

// =====================================================================
// CTA = (b, p, q, nh): rows [q*64,+64) x t-cols [nh*128,+128).
// 256 thr, 4 CTA/SM (64 regs/thread). Follower publishes half-red, exits.
// =====================================================================
__global__ void __launch_bounds__(256, 4)
da_fused_kernel(const float* __restrict__ x, const float* __restrict__ w,
                const float* __restrict__ gamma, const float* __restrict__ beta,
                float* __restrict__ out)
{
    extern __shared__ __align__(16) char sm[];
    const uint32_t smb = smem_to_u32(sm);
    const int tid = threadIdx.x, wid = tid >> 5, lane = tid & 31;
    const int bx = blockIdx.x;                 // 0..63 = b*8 + q*2 + nh
    const int nh = bx & 1, q = (bx >> 1) & 3, b = bx >> 3;
    const int p = blockIdx.y;
    const int m0 = q * 64;                     // global row base
    const int nb0 = nh * 128;                  // global t-col base
    const int pair = ((p * 8 + b) * 4 + q);
    const float* xbp = x + (size_t)(b * P_ + p) * (S_ * D_);
    const float* wp  = w + ((size_t)p << 16);

    // prefetch this CTA's W half-tile (32KB) into L2
    {
        const float* wt = wp + (size_t)(m0 + (tid >> 2)) * 256 + nb0 + (tid & 3) * 32;
        PF_L2(wt);
    }

    const int warp_m = wid >> 2;   // 0..1 : 32 m-rows
    const int warp_n = wid & 3;    // 0..3 : 32 n-cols

    // accumulators: 2 m-frags x 4 n-frags x 4 = 32 regs
    float acc[2][4][4];
    #pragma unroll
    for (int mi = 0; mi < 2; ++mi)
        #pragma unroll
        for (int nf = 0; nf < 4; ++nf)
            #pragma unroll
            for (int qq = 0; qq < 4; ++qq) acc[mi][nf][qq] = 0.f;

    const bool contained = ((q >> 1) == nh);   // A rows inside B slice?
    const uint32_t aBase = contained ? smb + (uint32_t)(m0 - nb0) * ROWB
                                     : smb + OFF_A;

    const uint32_t lrow = lane & 15;
    const uint32_t lcol = (lane >> 4) * 16;
    uint32_t aaddr[2], baddr[2];
    #pragma unroll
    for (int mi = 0; mi < 2; ++mi)
        aaddr[mi] = aBase + (uint32_t)(warp_m * 32 + mi * 16 + lrow) * ROWB + lcol;
    #pragma unroll
    for (int nj = 0; nj < 2; ++nj)
        baddr[nj] = smb + (uint32_t)(warp_n * 32 + nj * 16 + lrow) * ROWB + lcol;

    const int rbase = tid >> 4;    // 0..15
    const int c4    = tid & 15;    // float4 col within 64-k chunk

    // ================= k-chunk loop (4 chunks of K=64) =================
    for (int kc = 0; kc < 4; ++kc) {
        __syncthreads();
        // ---- B slice: 128 rows (two batches of 4 to cap register peak) ----
        #pragma unroll
        for (int h = 0; h < 2; ++h) {
            float4 pv[4];
            #pragma unroll
            for (int j = 0; j < 4; ++j)
                pv[j] = __ldg(reinterpret_cast<const float4*>(
                    xbp + (size_t)(nb0 + rbase + 16 * (h * 4 + j)) * D_ + kc * 64 + c4 * 4));
            #pragma unroll
            for (int j = 0; j < 4; ++j) {
                float4 v = pv[j];
                __nv_bfloat162 h01 = __floats2bfloat162_rn(v.x, v.y);
                __nv_bfloat162 h23 = __floats2bfloat162_rn(v.z, v.w);
                *reinterpret_cast<uint2*>(sm + (size_t)(rbase + 16 * (h * 4 + j)) * ROWB + c4 * 8) =
                    make_uint2(*reinterpret_cast<uint32_t*>(&h01),
                               *reinterpret_cast<uint32_t*>(&h23));
            }
        }
        // ---- A slice (64 rows) when disjoint ----
        if (!contained) {
            float4 pv[4];
            #pragma unroll
            for (int j = 0; j < 4; ++j)
                pv[j] = __ldg(reinterpret_cast<const float4*>(
                    xbp + (size_t)(m0 + rbase + 16 * j) * D_ + kc * 64 + c4 * 4));
            #pragma unroll
            for (int j = 0; j < 4; ++j) {
                float4 v = pv[j];
                __nv_bfloat162 h01 = __floats2bfloat162_rn(v.x, v.y);
                __nv_bfloat162 h23 = __floats2bfloat162_rn(v.z, v.w);
                *reinterpret_cast<uint2*>(sm + OFF_A + (size_t)(rbase + 16 * j) * ROWB + c4 * 8) =
                    make_uint2(*reinterpret_cast<uint32_t*>(&h01),
                               *reinterpret_cast<uint32_t*>(&h23));
            }
        }
        __syncthreads();

        #pragma unroll
        for (int ks = 0; ks < 4; ++ks) {
            const uint32_t ko = (uint32_t)ks * 32;
            uint32_t ah[2][4], bh[2][4];
            #pragma unroll
            for (int mi = 0; mi < 2; ++mi)
                LDSM4(ah[mi][0], ah[mi][1], ah[mi][2], ah[mi][3], aaddr[mi] + ko);
            #pragma unroll
            for (int nj = 0; nj < 2; ++nj)
                LDSM4(bh[nj][0], bh[nj][1], bh[nj][2], bh[nj][3], baddr[nj] + ko);
            #pragma unroll
            for (int nj = 0; nj < 2; ++nj)
                #pragma unroll
                for (int nk = 0; nk < 2; ++nk) {
                    const int nf = nj * 2 + nk;
                    #pragma unroll
                    for (int mi = 0; mi < 2; ++mi)
                        HMMA(acc[mi][nf], ah[mi][0], ah[mi][1], ah[mi][2], ah[mi][3],
                             bh[nj][nk], bh[nj][2 + nk]);
                }
        }
    }
    __syncthreads();   // buffer dead -> overlay usable

    // ================= fold W (own n-half) into per-row partials =================
    float* redp = reinterpret_cast<float*>(sm + OFF_REDP);
    #pragma unroll
    for (int mi = 0; mi < 2; ++mi)
        #pragma unroll
        for (int half = 0; half < 2; ++half) {
            int rl = warp_m * 32 + mi * 16 + (lane >> 2) + half * 8;   // 0..63 local
            const float* wr = wp + (size_t)(m0 + rl) * 256 + nb0 + warp_n * 32 + (lane & 3) * 2;
            float part = 0.f;
            #pragma unroll
            for (int nf = 0; nf < 4; ++nf) {
                float2 wv = __ldg(reinterpret_cast<const float2*>(
                    wr + (nf >> 1) * 16 + (nf & 1) * 8));
                part = fmaf(acc[mi][nf][half * 2 + 0], wv.x, part);
                part = fmaf(acc[mi][nf][half * 2 + 1], wv.y, part);
            }
            redp[rl * 17 + warp_n * 4 + (lane & 3)] = part;
        }
    __syncthreads();

    // reduce 16 partials per row -> this CTA's (unscaled) half-red
    float rsum = 0.f;
    if (tid < 64) {
        #pragma unroll
        for (int l = 0; l < 16; ++l) rsum += redp[tid * 17 + l];
    }

    // ================= follower: publish half-red and exit =================
    if (nh == 1) {
        if (tid < 64) {
            g_redhalf[pair * 64 + tid] = rsum;
            __threadfence();
        }
        __syncthreads();
        if (tid == 0) atomicExch(&g_pflag[pair], 1);
        return;
    }

    // ================= leader: row sums of x (direct from global) =================
    float* rssm = reinterpret_cast<float*>(sm + OFF_RS);
    float* s2sm = reinterpret_cast<float*>(sm + OFF_S2);
    #pragma unroll
    for (int j = 0; j < 8; ++j) {
        int r = wid * 8 + j;                       // 0..63 local
        const float* xr = xbp + (size_t)(m0 + r) * 256;
        float4 v0 = __ldg(reinterpret_cast<const float4*>(xr + lane * 4));
        float4 v1 = __ldg(reinterpret_cast<const float4*>(xr + 128 + lane * 4));
        float rsv = v0.x + v0.y + v0.z + v0.w + v1.x + v1.y + v1.z + v1.w;
        float s2v = v0.x * v0.x + v0.y * v0.y + v0.z * v0.z + v0.w * v0.w
                  + v1.x * v1.x + v1.y * v1.y + v1.z * v1.z + v1.w * v1.w;
        #pragma unroll
        for (int o = 16; o; o >>= 1) {
            rsv += __shfl_xor_sync(0xffffffffu, rsv, o);
            s2v += __shfl_xor_sync(0xffffffffu, s2v, o);
        }
        if (lane == 0) { rssm[r] = rsv; s2sm[r] = s2v; }
    }

    // wait for sibling's half-red
    if (tid == 0) {
        volatile int* fl = (volatile int*)&g_pflag[pair];
        while (*fl == 0) __nanosleep(32);
        __threadfence();
    }
    __syncthreads();

    // ================= merge red + BN vals =================
    float* redsm = reinterpret_cast<float*>(sm + OFF_RED);
    float vals[5] = {0.f, 0.f, 0.f, 0.f, 0.f};
    if (tid < 64) {
        float sib = g_redhalf[pair * 64 + tid];
        float red = (rsum + sib) * 0.0625f;     // 1/sqrt(256)
        redsm[tid] = red;
        float xr = rssm[tid], x2 = s2sm[tid];
        vals[0] = xr; vals[1] = x2; vals[2] = red; vals[3] = red * red; vals[4] = red * xr;
    }
    float* w8 = reinterpret_cast<float*>(sm + OFF_W8);
    #pragma unroll
    for (int qq = 0; qq < 5; ++qq) {
        float v = vals[qq];
        #pragma unroll
        for (int o = 16; o; o >>= 1) v += __shfl_xor_sync(0xffffffffu, v, o);
        if (lane == 0) w8[wid * 5 + qq] = v;
    }
    __syncthreads();
    if (tid == 32) g_pflag[pair] = 0;          // reset for next graph replay

    // ================= cross-CTA BN handshake (32 leaders per channel) =================
    float* bc = reinterpret_cast<float*>(sm + OFF_BC);
    if (tid == 0) {
        int slot = (p * 32 + b * 4 + q) * 5;
        #pragma unroll
        for (int qq = 0; qq < 5; ++qq) {
            float r = 0.f;
            for (int t = 0; t < 8; ++t) r += w8[t * 5 + qq];
            g_partials[slot + qq] = r;
        }
        __threadfence();
        int o = atomicAdd(&g_cnt[p], 1);
        if (o == 31) {
            __threadfence();
            float sx = 0.f, sx2 = 0.f, sr = 0.f, sr2 = 0.f, cr = 0.f;
            for (int c = 0; c < 32; ++c) {
                const float* qp = g_partials + (p * 32 + c) * 5;
                sx += qp[0]; sx2 += qp[1]; sr += qp[2]; sr2 += qp[3]; cr += qp[4];
            }
            const float N = (float)(B_ * S_ * D_);
            float sumy  = sx + (float)D_ * sr;
            float sumy2 = sx2 + 2.f * cr + (float)D_ * sr2;
            float mean = sumy / N;
            float var  = sumy2 / N - mean * mean;
            float sc = __ldg(gamma + p) * rsqrtf(var + 1e-5f);
            g_scale[p] = sc;
            g_bias[p]  = __ldg(beta + p) - mean * sc;
            __threadfence();
            atomicExch(&g_flag[p], 1);
        }
        volatile int* fl = (volatile int*)&g_flag[p];
        while (*fl == 0) __nanosleep(64);
        __threadfence();
        bc[0] = g_scale[p];
        bc[1] = g_bias[p];
        int o2 = atomicAdd(&g_cnt2[p], 1);
        if (o2 == 31) {        // all consumers done: reset for next graph replay
            g_flag[p] = 0; g_cnt[p] = 0; g_cnt2[p] = 0;
        }
    }
    __syncthreads();
    const float sc = bc[0], bi = bc[1];

    // ================= output: out = (x + red) * sc + bi (x direct from L2) =================
    float* ob = out + ((size_t)(b * P_ + p) << 16) + (size_t)m0 * 256;
    #pragma unroll
    for (int j = 0; j < 8; ++j) {
        int r = wid * 8 + j;
        float red = redsm[r];
        const float* xr = xbp + (size_t)(m0 + r) * 256;
        #pragma unroll
        for (int it = 0; it < 2; ++it) {
            float4 v = __ldg(reinterpret_cast<const float4*>(xr + it * 128 + lane * 4));
            v.x = fmaf(v.x + red, sc, bi);
            v.y = fmaf(v.y + red, sc, bi);
            v.z = fmaf(v.z + red, sc, bi);
            v.w = fmaf(v.w + red, sc, bi);
            *reinterpret_cast<float4*>(ob + (size_t)r * 256 + it * 128 + lane * 4) = v;
        }
    }
}

// =====================================================================
extern "C" void kernel_launch(void* const* d_in, const int* in_sizes, int n_in,
                              void* d_out, int out_size)
{
    const float* x     = (const float*)d_in[0];
    const float* w     = (const float*)d_in[1];
    const float* gamma = (const float*)d_in[2];
    const float* beta  = (const float*)d_in[3];
    float* out = (float*)d_out;

    cudaFuncSetAttribute(da_fused_kernel,
                         cudaFuncAttributeMaxDynamicSharedMemorySize, SMEM_BYTES);

    dim3 grid(64, P_);   // blockIdx.x = b*8+q*2+nh (pairs adjacent, channels contiguous)
    da_fused_kernel<<<grid, 256, SMEM_BYTES>>>(x, w, gamma, beta, out);
}